// round 2
// baseline (speedup 1.0000x reference)
#include <cuda_runtime.h>
#include <math.h>

// Problem constants
#define NCH   64          // B*C chains
#define NN    512
#define TT    64
#define NT    32768       // NN*TT per chain
#define RR    66          // number of basis matrices
#define SEGS  4
#define SEGLEN 8192       // NT/SEGS
#define BUFSZ ((size_t)NCH * (size_t)NT)   // elems per r-buffer

// Scratch (device globals; allocation-free per harness rules)
__device__ float g_R[(size_t)RR * (size_t)NCH * (size_t)NT];  // 553 MB: all basis buffers (unnormalized)
__device__ float g_W[(size_t)NCH * (size_t)NT];               // GEMM workspace (8 MB)
__device__ float g_pn[RR][NCH][SEGS];                         // partial sum-of-squares per buffer
__device__ float g_pd[NCH][SEGS][3];                          // partial dots for current step
__device__ float g_theta[4][RR];
__device__ float g_wt[33][64];                                // transposed effective MLP weights + bias row

// ---------------- block reduction (256 threads) ----------------
__device__ __forceinline__ float blockReduce256(float v) {
    __shared__ float sh[8];
    __syncthreads();   // protect sh against reuse across calls
    #pragma unroll
    for (int o = 16; o > 0; o >>= 1) v += __shfl_down_sync(0xffffffffu, v, o);
    if ((threadIdx.x & 31) == 0) sh[threadIdx.x >> 5] = v;
    __syncthreads();
    if (threadIdx.x == 0) {
        float s = 0.f;
        #pragma unroll
        for (int i = 0; i < 8; i++) s += sh[i];
        sh[0] = s;
    }
    __syncthreads();
    return sh[0];
}

// ---------------- prep: theta MLP + folded BN weights ----------------
__global__ void prep_kernel(const float* __restrict__ STE,
                            const float* __restrict__ w1, const float* __restrict__ b1,
                            const float* __restrict__ w2, const float* __restrict__ b2,
                            const float* __restrict__ wm, const float* __restrict__ bm,
                            const float* __restrict__ gam, const float* __restrict__ bet,
                            const float* __restrict__ mean, const float* __restrict__ var) {
    int tid = threadIdx.x;
    if (tid < 4 * RR) {
        int b = tid / RR, r = tid % RR;
        int qq = r / 11, pp = r % 11;
        float acc = b2[pp];
        #pragma unroll
        for (int p = 0; p < 10; p++) {
            float h1 = b1[qq];
            #pragma unroll
            for (int t = 0; t < 5; t++) h1 += w1[qq * 5 + t] * STE[(b * 5 + t) * 10 + p];
            acc += w2[pp * 10 + p] * h1;
        }
        g_theta[b][r] = fmaxf(acc, 0.f);
    }
    if (tid < 64) {
        int o = tid;
        float inv = gam[o] * rsqrtf(var[o] + 1e-5f);
        for (int c = 0; c < 32; c++) g_wt[c][o] = wm[o * 32 + c] * inv;
        g_wt[32][o] = bm[o] * inv + bet[o] - mean[o] * inv;
    }
}

// ---------------- init: m00 = x / max(||x||, eps) ----------------
__global__ void init_kernel(const float* __restrict__ x) {
    int chain = blockIdx.x;
    const float4* xg = (const float4*)(x + (size_t)chain * NT);
    float ss = 0.f;
    for (int i = threadIdx.x; i < NT / 4; i += 256) {
        float4 v = xg[i];
        ss += v.x * v.x + v.y * v.y + v.z * v.z + v.w * v.w;
    }
    ss = blockReduce256(ss);
    float s = 1.f / fmaxf(sqrtf(ss), 1e-8f);
    float4* r = (float4*)(g_R + (size_t)chain * NT);
    for (int i = threadIdx.x; i < NT / 4; i += 256) {
        float4 v = xg[i];
        v.x *= s; v.y *= s; v.z *= s; v.w *= s;
        r[i] = v;
    }
    if (threadIdx.x == 0) {
        g_pn[0][chain][0] = 1.f;
        g_pn[0][chain][1] = 0.f; g_pn[0][chain][2] = 0.f; g_pn[0][chain][3] = 0.f;
    }
}

// ---------------- spatial GEMM: W[c][n][t] = sum_m L[n][m] * R[c][m][t] ----------------
// grid (4 n-tiles of 128, 64 chains), 256 threads, 8x4 thread tile, K-chunk 16
__global__ void __launch_bounds__(256) spatial_gemm(const float* __restrict__ L, int lastIdx) {
    __shared__ float As[16][128];
    __shared__ float Bs[16][64];
    int chain = blockIdx.y;
    int n0 = blockIdx.x * 128;
    const float* Bg = g_R + (size_t)lastIdx * BUFSZ + (size_t)chain * NT;
    int tid = threadIdx.x;
    int ty = tid >> 4, tx = tid & 15;
    float acc[8][4];
    #pragma unroll
    for (int i = 0; i < 8; i++)
        #pragma unroll
        for (int j = 0; j < 4; j++) acc[i][j] = 0.f;

    for (int k0 = 0; k0 < 512; k0 += 16) {
        #pragma unroll
        for (int s = 0; s < 2; s++) {
            int lin = tid * 2 + s;          // 0..511
            int row = lin >> 2, c4 = lin & 3;
            float4 v = *(const float4*)(L + (size_t)(n0 + row) * 512 + k0 + c4 * 4);
            As[c4 * 4 + 0][row] = v.x;
            As[c4 * 4 + 1][row] = v.y;
            As[c4 * 4 + 2][row] = v.z;
            As[c4 * 4 + 3][row] = v.w;
        }
        {
            int k = tid >> 4, t4 = tid & 15;
            *(float4*)&Bs[k][t4 * 4] = *(const float4*)(Bg + (size_t)(k0 + k) * 64 + t4 * 4);
        }
        __syncthreads();
        #pragma unroll
        for (int k = 0; k < 16; k++) {
            float4 a0 = *(const float4*)&As[k][ty * 8];
            float4 a1 = *(const float4*)&As[k][ty * 8 + 4];
            float4 bv = *(const float4*)&Bs[k][tx * 4];
            float av[8] = {a0.x, a0.y, a0.z, a0.w, a1.x, a1.y, a1.z, a1.w};
            float bb[4] = {bv.x, bv.y, bv.z, bv.w};
            #pragma unroll
            for (int i = 0; i < 8; i++)
                #pragma unroll
                for (int j = 0; j < 4; j++) acc[i][j] += av[i] * bb[j];
        }
        __syncthreads();
    }
    float* Wg = g_W + (size_t)chain * NT;
    #pragma unroll
    for (int i = 0; i < 8; i++) {
        int n = n0 + ty * 8 + i;
        *(float4*)(Wg + (size_t)n * 64 + tx * 4) =
            make_float4(acc[i][0], acc[i][1], acc[i][2], acc[i][3]);
    }
}

// ---------------- temporal GEMM: W[c][n][u] = sum_t R[c][n][t] * Lt[t][u] ----------------
// grid (8 row-tiles of 64, 64 chains), 256 threads, 4x4 thread tile
__global__ void __launch_bounds__(256) temporal_gemm(const float* __restrict__ Lt, int lastIdx) {
    __shared__ float Lts[64][64];
    __shared__ float As[64][64];
    int chain = blockIdx.y;
    int r0 = blockIdx.x * 64;
    const float* Ag = g_R + (size_t)lastIdx * BUFSZ + (size_t)chain * NT + (size_t)r0 * 64;
    int tid = threadIdx.x;
    for (int i = tid; i < 1024; i += 256) ((float4*)Lts)[i] = ((const float4*)Lt)[i];
    for (int i = tid; i < 1024; i += 256) ((float4*)As)[i] = ((const float4*)Ag)[i];
    __syncthreads();
    int ty = tid >> 4, tx = tid & 15;
    float acc[4][4];
    #pragma unroll
    for (int i = 0; i < 4; i++)
        #pragma unroll
        for (int j = 0; j < 4; j++) acc[i][j] = 0.f;

    #pragma unroll 4
    for (int t0 = 0; t0 < 64; t0 += 4) {
        float4 b0 = *(const float4*)&Lts[t0 + 0][tx * 4];
        float4 b1 = *(const float4*)&Lts[t0 + 1][tx * 4];
        float4 b2 = *(const float4*)&Lts[t0 + 2][tx * 4];
        float4 b3 = *(const float4*)&Lts[t0 + 3][tx * 4];
        #pragma unroll
        for (int i = 0; i < 4; i++) {
            float4 a = *(const float4*)&As[ty * 4 + i][t0];
            acc[i][0] += a.x * b0.x + a.y * b1.x + a.z * b2.x + a.w * b3.x;
            acc[i][1] += a.x * b0.y + a.y * b1.y + a.z * b2.y + a.w * b3.y;
            acc[i][2] += a.x * b0.z + a.y * b1.z + a.z * b2.z + a.w * b3.z;
            acc[i][3] += a.x * b0.w + a.y * b1.w + a.z * b2.w + a.w * b3.w;
        }
    }
    float* Wg = g_W + (size_t)chain * NT + (size_t)r0 * 64;
    #pragma unroll
    for (int i = 0; i < 4; i++)
        *(float4*)(Wg + (size_t)(ty * 4 + i) * 64 + tx * 4) =
            make_float4(acc[i][0], acc[i][1], acc[i][2], acc[i][3]);
}

// ---------------- dots: partial <W,Rl>, <W,Rs>, <Rl,Rs> ----------------
__global__ void dots_kernel(int lastIdx, int secIdx) {
    int chain = blockIdx.y, seg = blockIdx.x;
    size_t base = (size_t)chain * NT + (size_t)seg * SEGLEN;
    const float4* w = (const float4*)(g_W + base);
    const float4* a = (const float4*)(g_R + (size_t)lastIdx * BUFSZ + base);
    float d1 = 0.f, d2 = 0.f, d3 = 0.f;
    if (secIdx >= 0) {
        const float4* s = (const float4*)(g_R + (size_t)secIdx * BUFSZ + base);
        for (int i = threadIdx.x; i < SEGLEN / 4; i += 256) {
            float4 wv = w[i], av = a[i], sv = s[i];
            d1 += wv.x * av.x + wv.y * av.y + wv.z * av.z + wv.w * av.w;
            d2 += wv.x * sv.x + wv.y * sv.y + wv.z * sv.z + wv.w * sv.w;
            d3 += av.x * sv.x + av.y * sv.y + av.z * sv.z + av.w * sv.w;
        }
    } else {
        for (int i = threadIdx.x; i < SEGLEN / 4; i += 256) {
            float4 wv = w[i], av = a[i];
            d1 += wv.x * av.x + wv.y * av.y + wv.z * av.z + wv.w * av.w;
        }
    }
    d1 = blockReduce256(d1);
    d2 = blockReduce256(d2);
    d3 = blockReduce256(d3);
    if (threadIdx.x == 0) {
        g_pd[chain][seg][0] = d1;
        g_pd[chain][seg][1] = d2;
        g_pd[chain][seg][2] = d3;
    }
}

// ---------------- update: R_new = c1*W + c2*R_last + c3*R_sec ; norm partials ----------------
__global__ void update_kernel(int lastIdx, int secIdx, int outIdx) {
    int chain = blockIdx.y, seg = blockIdx.x;
    __shared__ float cf[3];
    if (threadIdx.x == 0) {
        float pnl = g_pn[lastIdx][chain][0] + g_pn[lastIdx][chain][1] +
                    g_pn[lastIdx][chain][2] + g_pn[lastIdx][chain][3];
        float sl = 1.f / fmaxf(sqrtf(pnl), 1e-8f);
        float D1 = g_pd[chain][0][0] + g_pd[chain][1][0] + g_pd[chain][2][0] + g_pd[chain][3][0];
        float d1 = sl * sl * D1;
        float c3 = 0.f;
        if (secIdx >= 0) {
            float pns = g_pn[secIdx][chain][0] + g_pn[secIdx][chain][1] +
                        g_pn[secIdx][chain][2] + g_pn[secIdx][chain][3];
            float ssc = 1.f / fmaxf(sqrtf(pns), 1e-8f);
            float D2 = g_pd[chain][0][1] + g_pd[chain][1][1] + g_pd[chain][2][1] + g_pd[chain][3][1];
            float D3 = g_pd[chain][0][2] + g_pd[chain][1][2] + g_pd[chain][2][2] + g_pd[chain][3][2];
            float d2 = sl * ssc * D2;
            float d3 = sl * ssc * D3;
            c3 = -(d2 - d1 * d3) * ssc;
        }
        cf[0] = sl;
        cf[1] = -d1 * sl;
        cf[2] = c3;
    }
    __syncthreads();
    float c1 = cf[0], c2 = cf[1], c3 = cf[2];
    size_t base = (size_t)chain * NT + (size_t)seg * SEGLEN;
    const float4* w = (const float4*)(g_W + base);
    const float4* a = (const float4*)(g_R + (size_t)lastIdx * BUFSZ + base);
    float4* o = (float4*)(g_R + (size_t)outIdx * BUFSZ + base);
    float nrm = 0.f;
    if (secIdx >= 0) {
        const float4* s = (const float4*)(g_R + (size_t)secIdx * BUFSZ + base);
        for (int i = threadIdx.x; i < SEGLEN / 4; i += 256) {
            float4 wv = w[i], av = a[i], sv = s[i];
            float4 rv;
            rv.x = c1 * wv.x + c2 * av.x + c3 * sv.x;
            rv.y = c1 * wv.y + c2 * av.y + c3 * sv.y;
            rv.z = c1 * wv.z + c2 * av.z + c3 * sv.z;
            rv.w = c1 * wv.w + c2 * av.w + c3 * sv.w;
            o[i] = rv;
            nrm += rv.x * rv.x + rv.y * rv.y + rv.z * rv.z + rv.w * rv.w;
        }
    } else {
        for (int i = threadIdx.x; i < SEGLEN / 4; i += 256) {
            float4 wv = w[i], av = a[i];
            float4 rv;
            rv.x = c1 * wv.x + c2 * av.x;
            rv.y = c1 * wv.y + c2 * av.y;
            rv.z = c1 * wv.z + c2 * av.z;
            rv.w = c1 * wv.w + c2 * av.w;
            o[i] = rv;
            nrm += rv.x * rv.x + rv.y * rv.y + rv.z * rv.z + rv.w * rv.w;
        }
    }
    nrm = blockReduce256(nrm);
    if (threadIdx.x == 0) g_pn[outIdx][chain][seg] = nrm;
}

// ---------------- final: x_st = sum_r theta*s_r*R_r ; MLP + BN fused ----------------
// grid (128 n-groups of 4, 4 b), 256 threads = 4 n x 64 t
__global__ void final_kernel(const float* __restrict__ x, float* __restrict__ out) {
    __shared__ float coef[RR][16];
    __shared__ float wsh[33][64];
    int b = blockIdx.y;
    int tid = threadIdx.x;
    for (int idx = tid; idx < RR * 16; idx += 256) {
        int r = idx >> 4, f = idx & 15;
        int c = b * 16 + f;
        float pn = g_pn[r][c][0] + g_pn[r][c][1] + g_pn[r][c][2] + g_pn[r][c][3];
        float s = 1.f / fmaxf(sqrtf(pn), 1e-8f);
        coef[r][f] = g_theta[b][r] * s;
    }
    for (int idx = tid; idx < 33 * 64; idx += 256) ((float*)wsh)[idx] = ((const float*)g_wt)[idx];
    __syncthreads();

    int n = blockIdx.x * 4 + (tid >> 6);
    int t = tid & 63;
    int e = n * 64 + t;
    float yo[64];
    #pragma unroll
    for (int o = 0; o < 64; o++) yo[o] = wsh[32][o];

    #pragma unroll 1
    for (int f = 0; f < 16; f++) {
        size_t cb = (size_t)(b * 16 + f) * NT + e;
        float xv = x[cb];
        float xs = 0.f;
        #pragma unroll 11
        for (int r = 0; r < RR; r++) xs += coef[r][f] * g_R[(size_t)r * BUFSZ + cb];
        #pragma unroll
        for (int o4 = 0; o4 < 16; o4++) {
            float4 w1 = *(const float4*)&wsh[f][o4 * 4];
            float4 w2 = *(const float4*)&wsh[16 + f][o4 * 4];
            yo[o4 * 4 + 0] += w1.x * xv + w2.x * xs;
            yo[o4 * 4 + 1] += w1.y * xv + w2.y * xs;
            yo[o4 * 4 + 2] += w1.z * xv + w2.z * xs;
            yo[o4 * 4 + 3] += w1.w * xv + w2.w * xs;
        }
    }
    size_t ob = (size_t)b * 64 * NT + e;
    #pragma unroll
    for (int o = 0; o < 64; o++) out[ob + (size_t)o * NT] = yo[o];
}

// ---------------- host orchestration ----------------
extern "C" void kernel_launch(void* const* d_in, const int* in_sizes, int n_in,
                              void* d_out, int out_size) {
    const float* x   = (const float*)d_in[0];
    const float* Ls  = (const float*)d_in[1];
    const float* Lt  = (const float*)d_in[2];
    const float* STE = (const float*)d_in[3];
    const float* w1  = (const float*)d_in[4];
    const float* b1  = (const float*)d_in[5];
    const float* w2  = (const float*)d_in[6];
    const float* b2  = (const float*)d_in[7];
    const float* wm  = (const float*)d_in[8];
    const float* bm  = (const float*)d_in[9];
    const float* gam = (const float*)d_in[10];
    const float* bet = (const float*)d_in[11];
    const float* mean= (const float*)d_in[12];
    const float* var = (const float*)d_in[13];
    float* out = (float*)d_out;

    prep_kernel<<<1, 320>>>(STE, w1, b1, w2, b2, wm, bm, gam, bet, mean, var);
    init_kernel<<<64, 256>>>(x);

    dim3 gE(SEGS, NCH);          // elementwise grids
    dim3 gS(4, NCH);             // spatial gemm grid
    dim3 gT(8, NCH);             // temporal gemm grid

    int last_s = 0, sec_s = -1, last_t = 0, sec_t = -1;
    int r = 1;
    for (int i = 0; i <= 10; i++) {
        if (i > 0) {
            spatial_gemm<<<gS, 256>>>(Ls, last_s);
            dots_kernel<<<gE, 256>>>(last_s, sec_s);
            update_kernel<<<gE, 256>>>(last_s, sec_s, r);
            sec_s = last_s; last_s = r;
            last_t = r; sec_t = -1;
            r++;
        }
        for (int j = 0; j < 5; j++) {
            temporal_gemm<<<gT, 256>>>(Lt, last_t);
            dots_kernel<<<gE, 256>>>(last_t, sec_t);
            update_kernel<<<gE, 256>>>(last_t, sec_t, r);
            sec_t = last_t; last_t = r;
            r++;
        }
    }
    final_kernel<<<dim3(128, 4), 256>>>(x, out);
}

// round 4
// speedup vs baseline: 1.0827x; 1.0827x over previous
#include <cuda_runtime.h>
#include <math.h>

#define NCH   64
#define NT    32768
#define RR    66
#define SEGS  4
#define SEGLEN 8192
#define BUFSZ ((size_t)NCH * (size_t)NT)

__device__ float g_R[(size_t)RR * BUFSZ];     // 553 MB basis buffers
__device__ float g_W[BUFSZ];                  // 8 MB GEMM workspace
__device__ float g_pn[RR][NCH][SEGS];         // norm^2 partials
__device__ float g_sd[RR][NCH][8][3];         // dot partials per gemm-block
__device__ float g_theta[4][RR];
__device__ float g_wt[33][64];

__device__ __forceinline__ float blockReduce256(float v) {
    __shared__ float sh[8];
    __syncthreads();
    #pragma unroll
    for (int o = 16; o > 0; o >>= 1) v += __shfl_down_sync(0xffffffffu, v, o);
    if ((threadIdx.x & 31) == 0) sh[threadIdx.x >> 5] = v;
    __syncthreads();
    if (threadIdx.x == 0) {
        float s = 0.f;
        #pragma unroll
        for (int i = 0; i < 8; i++) s += sh[i];
        sh[0] = s;
    }
    __syncthreads();
    return sh[0];
}

// ---------------- prep: theta MLP, folded BN, zero partial arrays ----------------
__global__ void prep_kernel(const float* __restrict__ STE,
                            const float* __restrict__ w1, const float* __restrict__ b1,
                            const float* __restrict__ w2, const float* __restrict__ b2,
                            const float* __restrict__ wm, const float* __restrict__ bm,
                            const float* __restrict__ gam, const float* __restrict__ bet,
                            const float* __restrict__ mean, const float* __restrict__ var) {
    int tid = threadIdx.x;
    if (tid < 4 * RR) {
        int b = tid / RR, r = tid % RR;
        int qq = r / 11, pp = r % 11;
        float acc = b2[pp];
        #pragma unroll
        for (int p = 0; p < 10; p++) {
            float h1 = b1[qq];
            #pragma unroll
            for (int t = 0; t < 5; t++) h1 += w1[qq * 5 + t] * STE[(b * 5 + t) * 10 + p];
            acc += w2[pp * 10 + p] * h1;
        }
        g_theta[b][r] = fmaxf(acc, 0.f);
    }
    if (tid < 64) {
        int o = tid;
        float inv = gam[o] * rsqrtf(var[o] + 1e-5f);
        for (int c = 0; c < 32; c++) g_wt[c][o] = wm[o * 32 + c] * inv;
        g_wt[32][o] = bm[o] * inv + bet[o] - mean[o] * inv;
    }
    float* pn = (float*)g_pn;
    for (int i = tid; i < RR * NCH * SEGS; i += blockDim.x) pn[i] = 0.f;
}

// ---------------- init: m00 = x / max(||x||, eps) ----------------
__global__ void init_kernel(const float* __restrict__ x) {
    int chain = blockIdx.x;
    const float4* xg = (const float4*)(x + (size_t)chain * NT);
    float ss = 0.f;
    for (int i = threadIdx.x; i < NT / 4; i += 256) {
        float4 v = xg[i];
        ss += v.x * v.x + v.y * v.y + v.z * v.z + v.w * v.w;
    }
    ss = blockReduce256(ss);
    float s = 1.f / fmaxf(sqrtf(ss), 1e-8f);
    float4* r = (float4*)(g_R + (size_t)chain * NT);
    for (int i = threadIdx.x; i < NT / 4; i += 256) {
        float4 v = xg[i];
        v.x *= s; v.y *= s; v.z *= s; v.w *= s;
        r[i] = v;
    }
    if (threadIdx.x == 0) g_pn[0][chain][0] = 1.f;
}

// ---------------- spatial GEMM + fused dot epilogue ----------------
// W[c][n][t] = sum_m L[n][m]*Rl[c][m][t];  d1=<W,Rl> d2=<W,Rs> d3=<Rl,Rs> partials
__global__ void __launch_bounds__(256) s_gemm_dots(const float* __restrict__ L,
                                                   int lastIdx, int secIdx, int slot) {
    __shared__ float As[16][128];
    __shared__ float Bs[16][64];
    int chain = blockIdx.y;
    int n0 = blockIdx.x * 128;
    const float* Bg = g_R + (size_t)lastIdx * BUFSZ + (size_t)chain * NT;
    int tid = threadIdx.x;
    int ty = tid >> 4, tx = tid & 15;
    float acc[8][4];
    #pragma unroll
    for (int i = 0; i < 8; i++)
        #pragma unroll
        for (int j = 0; j < 4; j++) acc[i][j] = 0.f;

    int lin0 = tid * 2, lin1 = tid * 2 + 1;
    int ar0 = lin0 >> 2, ac0 = lin0 & 3;
    int ar1 = lin1 >> 2, ac1 = lin1 & 3;
    int bk = tid >> 4, bt = tid & 15;
    float4 pa0 = *(const float4*)(L + (size_t)(n0 + ar0) * 512 + ac0 * 4);
    float4 pa1 = *(const float4*)(L + (size_t)(n0 + ar1) * 512 + ac1 * 4);
    float4 pb  = *(const float4*)(Bg + (size_t)bk * 64 + bt * 4);

    for (int k0 = 0; k0 < 512; k0 += 16) {
        As[ac0 * 4 + 0][ar0] = pa0.x; As[ac0 * 4 + 1][ar0] = pa0.y;
        As[ac0 * 4 + 2][ar0] = pa0.z; As[ac0 * 4 + 3][ar0] = pa0.w;
        As[ac1 * 4 + 0][ar1] = pa1.x; As[ac1 * 4 + 1][ar1] = pa1.y;
        As[ac1 * 4 + 2][ar1] = pa1.z; As[ac1 * 4 + 3][ar1] = pa1.w;
        *(float4*)&Bs[bk][bt * 4] = pb;
        __syncthreads();
        if (k0 + 16 < 512) {
            int kn = k0 + 16;
            pa0 = *(const float4*)(L + (size_t)(n0 + ar0) * 512 + kn + ac0 * 4);
            pa1 = *(const float4*)(L + (size_t)(n0 + ar1) * 512 + kn + ac1 * 4);
            pb  = *(const float4*)(Bg + (size_t)(kn + bk) * 64 + bt * 4);
        }
        #pragma unroll
        for (int k = 0; k < 16; k++) {
            float4 a0 = *(const float4*)&As[k][ty * 8];
            float4 a1 = *(const float4*)&As[k][ty * 8 + 4];
            float4 bv = *(const float4*)&Bs[k][tx * 4];
            float av[8] = {a0.x, a0.y, a0.z, a0.w, a1.x, a1.y, a1.z, a1.w};
            float bb[4] = {bv.x, bv.y, bv.z, bv.w};
            #pragma unroll
            for (int i = 0; i < 8; i++)
                #pragma unroll
                for (int j = 0; j < 4; j++) acc[i][j] += av[i] * bb[j];
        }
        __syncthreads();
    }
    float* Wg = g_W + (size_t)chain * NT;
    const float* Rl = g_R + (size_t)lastIdx * BUFSZ + (size_t)chain * NT;
    const float* Rs = (secIdx >= 0) ? g_R + (size_t)secIdx * BUFSZ + (size_t)chain * NT : 0;
    float d1 = 0.f, d2 = 0.f, d3 = 0.f;
    #pragma unroll
    for (int i = 0; i < 8; i++) {
        size_t off = (size_t)(n0 + ty * 8 + i) * 64 + tx * 4;
        *(float4*)(Wg + off) = make_float4(acc[i][0], acc[i][1], acc[i][2], acc[i][3]);
        float4 lv = *(const float4*)(Rl + off);
        d1 += acc[i][0] * lv.x + acc[i][1] * lv.y + acc[i][2] * lv.z + acc[i][3] * lv.w;
        if (Rs) {
            float4 sv = *(const float4*)(Rs + off);
            d2 += acc[i][0] * sv.x + acc[i][1] * sv.y + acc[i][2] * sv.z + acc[i][3] * sv.w;
            d3 += lv.x * sv.x + lv.y * sv.y + lv.z * sv.z + lv.w * sv.w;
        }
    }
    d1 = blockReduce256(d1);
    d2 = blockReduce256(d2);
    d3 = blockReduce256(d3);
    if (tid == 0) {
        g_sd[slot][chain][blockIdx.x][0] = d1;
        g_sd[slot][chain][blockIdx.x][1] = d2;
        g_sd[slot][chain][blockIdx.x][2] = d3;
    }
}

// ---------------- temporal GEMM + fused dot epilogue ----------------
// W[c][n][u] = sum_t Rl[c][n][t]*Lt[t][u]
__global__ void __launch_bounds__(256) t_gemm_dots(const float* __restrict__ Lt,
                                                   int lastIdx, int secIdx, int slot) {
    __shared__ float Lts[64][64];
    __shared__ float As[64][64];
    int chain = blockIdx.y;
    int r0 = blockIdx.x * 64;
    const float* Ag = g_R + (size_t)lastIdx * BUFSZ + (size_t)chain * NT + (size_t)r0 * 64;
    int tid = threadIdx.x;
    for (int i = tid; i < 1024; i += 256) ((float4*)Lts)[i] = ((const float4*)Lt)[i];
    for (int i = tid; i < 1024; i += 256) ((float4*)As)[i] = ((const float4*)Ag)[i];
    __syncthreads();
    int ty = tid >> 4, tx = tid & 15;
    float acc[4][4];
    #pragma unroll
    for (int i = 0; i < 4; i++)
        #pragma unroll
        for (int j = 0; j < 4; j++) acc[i][j] = 0.f;

    #pragma unroll 4
    for (int t0 = 0; t0 < 64; t0 += 4) {
        float4 b0 = *(const float4*)&Lts[t0 + 0][tx * 4];
        float4 b1 = *(const float4*)&Lts[t0 + 1][tx * 4];
        float4 b2 = *(const float4*)&Lts[t0 + 2][tx * 4];
        float4 b3 = *(const float4*)&Lts[t0 + 3][tx * 4];
        #pragma unroll
        for (int i = 0; i < 4; i++) {
            float4 a = *(const float4*)&As[ty * 4 + i][t0];
            acc[i][0] += a.x * b0.x + a.y * b1.x + a.z * b2.x + a.w * b3.x;
            acc[i][1] += a.x * b0.y + a.y * b1.y + a.z * b2.y + a.w * b3.y;
            acc[i][2] += a.x * b0.z + a.y * b1.z + a.z * b2.z + a.w * b3.z;
            acc[i][3] += a.x * b0.w + a.y * b1.w + a.z * b2.w + a.w * b3.w;
        }
    }
    float* Wg = g_W + (size_t)chain * NT + (size_t)r0 * 64;
    const float* Rs = (secIdx >= 0)
        ? g_R + (size_t)secIdx * BUFSZ + (size_t)chain * NT + (size_t)r0 * 64 : 0;
    float d1 = 0.f, d2 = 0.f, d3 = 0.f;
    #pragma unroll
    for (int i = 0; i < 4; i++) {
        int row = ty * 4 + i;
        *(float4*)(Wg + (size_t)row * 64 + tx * 4) =
            make_float4(acc[i][0], acc[i][1], acc[i][2], acc[i][3]);
        float4 lv = *(const float4*)&As[row][tx * 4];   // Rl tile already in smem
        d1 += acc[i][0] * lv.x + acc[i][1] * lv.y + acc[i][2] * lv.z + acc[i][3] * lv.w;
        if (Rs) {
            float4 sv = *(const float4*)(Rs + (size_t)row * 64 + tx * 4);
            d2 += acc[i][0] * sv.x + acc[i][1] * sv.y + acc[i][2] * sv.z + acc[i][3] * sv.w;
            d3 += lv.x * sv.x + lv.y * sv.y + lv.z * sv.z + lv.w * sv.w;
        }
    }
    d1 = blockReduce256(d1);
    d2 = blockReduce256(d2);
    d3 = blockReduce256(d3);
    if (tid == 0) {
        g_sd[slot][chain][blockIdx.x][0] = d1;
        g_sd[slot][chain][blockIdx.x][1] = d2;
        g_sd[slot][chain][blockIdx.x][2] = d3;
    }
}

// ---------------- update: R_new = c1*W + c2*Rl + c3*Rs ; norm partials ----------------
__global__ void update_kernel(int lastIdx, int secIdx, int outIdx, int npart) {
    int chain = blockIdx.y, seg = blockIdx.x;
    __shared__ float cf[3];
    if (threadIdx.x == 0) {
        float pnl = g_pn[lastIdx][chain][0] + g_pn[lastIdx][chain][1] +
                    g_pn[lastIdx][chain][2] + g_pn[lastIdx][chain][3];
        float sl = 1.f / fmaxf(sqrtf(pnl), 1e-8f);
        float D1 = 0.f, D2 = 0.f, D3 = 0.f;
        for (int p = 0; p < npart; p++) {
            D1 += g_sd[outIdx][chain][p][0];
            D2 += g_sd[outIdx][chain][p][1];
            D3 += g_sd[outIdx][chain][p][2];
        }
        float d1 = sl * sl * D1;
        float c3 = 0.f;
        if (secIdx >= 0) {
            float pns = g_pn[secIdx][chain][0] + g_pn[secIdx][chain][1] +
                        g_pn[secIdx][chain][2] + g_pn[secIdx][chain][3];
            float ssc = 1.f / fmaxf(sqrtf(pns), 1e-8f);
            float d2 = sl * ssc * D2;
            float d3 = sl * ssc * D3;
            c3 = -(d2 - d1 * d3) * ssc;
        }
        cf[0] = sl;
        cf[1] = -d1 * sl;
        cf[2] = c3;
    }
    __syncthreads();
    float c1 = cf[0], c2 = cf[1], c3 = cf[2];
    size_t base = (size_t)chain * NT + (size_t)seg * SEGLEN;
    const float4* w = (const float4*)(g_W + base);
    const float4* a = (const float4*)(g_R + (size_t)lastIdx * BUFSZ + base);
    float4* o = (float4*)(g_R + (size_t)outIdx * BUFSZ + base);
    float nrm = 0.f;
    if (secIdx >= 0) {
        const float4* s = (const float4*)(g_R + (size_t)secIdx * BUFSZ + base);
        for (int i = threadIdx.x; i < SEGLEN / 4; i += 256) {
            float4 wv = w[i], av = a[i], sv = s[i];
            float4 rv;
            rv.x = c1 * wv.x + c2 * av.x + c3 * sv.x;
            rv.y = c1 * wv.y + c2 * av.y + c3 * sv.y;
            rv.z = c1 * wv.z + c2 * av.z + c3 * sv.z;
            rv.w = c1 * wv.w + c2 * av.w + c3 * sv.w;
            o[i] = rv;
            nrm += rv.x * rv.x + rv.y * rv.y + rv.z * rv.z + rv.w * rv.w;
        }
    } else {
        for (int i = threadIdx.x; i < SEGLEN / 4; i += 256) {
            float4 wv = w[i], av = a[i];
            float4 rv;
            rv.x = c1 * wv.x + c2 * av.x;
            rv.y = c1 * wv.y + c2 * av.y;
            rv.z = c1 * wv.z + c2 * av.z;
            rv.w = c1 * wv.w + c2 * av.w;
            o[i] = rv;
            nrm += rv.x * rv.x + rv.y * rv.y + rv.z * rv.z + rv.w * rv.w;
        }
    }
    nrm = blockReduce256(nrm);
    if (threadIdx.x == 0) g_pn[outIdx][chain][seg] = nrm;
}

// ---------------- final: x_st + MLP + BN fused ----------------
__global__ void final_kernel(const float* __restrict__ x, float* __restrict__ out) {
    __shared__ float coef[RR][16];
    __shared__ float wsh[33][64];
    int b = blockIdx.y;
    int tid = threadIdx.x;
    for (int idx = tid; idx < RR * 16; idx += 256) {
        int r = idx >> 4, f = idx & 15;
        int c = b * 16 + f;
        float pn = g_pn[r][c][0] + g_pn[r][c][1] + g_pn[r][c][2] + g_pn[r][c][3];
        float s = 1.f / fmaxf(sqrtf(pn), 1e-8f);
        coef[r][f] = g_theta[b][r] * s;
    }
    for (int idx = tid; idx < 33 * 64; idx += 256) ((float*)wsh)[idx] = ((const float*)g_wt)[idx];
    __syncthreads();

    int n = blockIdx.x * 4 + (tid >> 6);
    int t = tid & 63;
    int e = n * 64 + t;
    float yo[64];
    #pragma unroll
    for (int o = 0; o < 64; o++) yo[o] = wsh[32][o];

    #pragma unroll 1
    for (int f = 0; f < 16; f++) {
        size_t cb = (size_t)(b * 16 + f) * NT + e;
        float xv = x[cb];
        float xs = 0.f;
        #pragma unroll 11
        for (int r = 0; r < RR; r++) xs += coef[r][f] * g_R[(size_t)r * BUFSZ + cb];
        #pragma unroll
        for (int o4 = 0; o4 < 16; o4++) {
            float4 w1 = *(const float4*)&wsh[f][o4 * 4];
            float4 w2 = *(const float4*)&wsh[16 + f][o4 * 4];
            yo[o4 * 4 + 0] += w1.x * xv + w2.x * xs;
            yo[o4 * 4 + 1] += w1.y * xv + w2.y * xs;
            yo[o4 * 4 + 2] += w1.z * xv + w2.z * xs;
            yo[o4 * 4 + 3] += w1.w * xv + w2.w * xs;
        }
    }
    size_t ob = (size_t)b * 64 * NT + e;
    #pragma unroll
    for (int o = 0; o < 64; o++) out[ob + (size_t)o * NT] = yo[o];
}

// ---------------- host orchestration ----------------
extern "C" void kernel_launch(void* const* d_in, const int* in_sizes, int n_in,
                              void* d_out, int out_size) {
    const float* x   = (const float*)d_in[0];
    const float* Ls  = (const float*)d_in[1];
    const float* Lt  = (const float*)d_in[2];
    const float* STE = (const float*)d_in[3];
    const float* w1  = (const float*)d_in[4];
    const float* b1  = (const float*)d_in[5];
    const float* w2  = (const float*)d_in[6];
    const float* b2  = (const float*)d_in[7];
    const float* wm  = (const float*)d_in[8];
    const float* bm  = (const float*)d_in[9];
    const float* gam = (const float*)d_in[10];
    const float* bet = (const float*)d_in[11];
    const float* mean= (const float*)d_in[12];
    const float* var = (const float*)d_in[13];
    float* out = (float*)d_out;

    prep_kernel<<<1, 320>>>(STE, w1, b1, w2, b2, wm, bm, gam, bet, mean, var);
    init_kernel<<<64, 256>>>(x);

    dim3 gE(SEGS, NCH);
    dim3 gS(4, NCH);
    dim3 gT(8, NCH);

    int last_s = 0, sec_s = -1, last_t = 0, sec_t = -1;
    int r = 1;
    for (int i = 0; i <= 10; i++) {
        if (i > 0) {
            s_gemm_dots<<<gS, 256>>>(Ls, last_s, sec_s, r);
            update_kernel<<<gE, 256>>>(last_s, sec_s, r, 4);
            sec_s = last_s; last_s = r;
            last_t = r; sec_t = -1;
            r++;
        }
        for (int j = 0; j < 5; j++) {
            t_gemm_dots<<<gT, 256>>>(Lt, last_t, sec_t, r);
            update_kernel<<<gE, 256>>>(last_t, sec_t, r, 8);
            sec_t = last_t; last_t = r;
            r++;
        }
    }
    final_kernel<<<dim3(128, 4), 256>>>(x, out);
}

// round 6
// speedup vs baseline: 1.2359x; 1.1415x over previous
#include <cuda_runtime.h>
#include <math.h>

#define NCH   64
#define NT    32768
#define RR    66
#define BUFSZ ((size_t)NCH * (size_t)NT)
#define NGRP  11

__device__ float g_R[(size_t)RR * BUFSZ];          // 553 MB basis buffers (raw)
__device__ float g_Wg[(size_t)NGRP * BUFSZ];       // 92 MB per-group GEMM workspace
__device__ float g_pn[RR][NCH][8];                 // norm^2 partials
__device__ float g_sd[RR][NCH][8][3];              // dot partials per gemm-block
__device__ float g_theta[4][RR];
__device__ float g_wt[33][64];

__device__ __forceinline__ float blockReduce256(float v) {
    __shared__ float sh[8];
    __syncthreads();
    #pragma unroll
    for (int o = 16; o > 0; o >>= 1) v += __shfl_down_sync(0xffffffffu, v, o);
    if ((threadIdx.x & 31) == 0) sh[threadIdx.x >> 5] = v;
    __syncthreads();
    if (threadIdx.x == 0) {
        float s = 0.f;
        #pragma unroll
        for (int i = 0; i < 8; i++) s += sh[i];
        sh[0] = s;
    }
    __syncthreads();
    return sh[0];
}

// Gram-Schmidt coefficients from stored partials (deferred normalization)
__device__ __forceinline__ void gs_coeffs(int updLast, int updSec, int outIdx,
                                          int npart, int chain, float* cf) {
    float pnl = 0.f;
    #pragma unroll
    for (int p = 0; p < 8; p++) pnl += g_pn[updLast][chain][p];
    float sl = 1.f / fmaxf(sqrtf(pnl), 1e-8f);
    float D1 = 0.f, D2 = 0.f, D3 = 0.f;
    for (int p = 0; p < npart; p++) {
        D1 += g_sd[outIdx][chain][p][0];
        D2 += g_sd[outIdx][chain][p][1];
        D3 += g_sd[outIdx][chain][p][2];
    }
    float d1 = sl * sl * D1;
    float c3 = 0.f;
    if (updSec >= 0) {
        float pns = 0.f;
        #pragma unroll
        for (int p = 0; p < 8; p++) pns += g_pn[updSec][chain][p];
        float ssc = 1.f / fmaxf(sqrtf(pns), 1e-8f);
        float dd2 = sl * ssc * D2;
        float dd3 = sl * ssc * D3;
        c3 = -(dd2 - d1 * dd3) * ssc;
    }
    cf[0] = sl; cf[1] = -d1 * sl; cf[2] = c3;
}

// ---------------- prep ----------------
__global__ void prep_kernel(const float* __restrict__ STE,
                            const float* __restrict__ w1, const float* __restrict__ b1,
                            const float* __restrict__ w2, const float* __restrict__ b2,
                            const float* __restrict__ wm, const float* __restrict__ bm,
                            const float* __restrict__ gam, const float* __restrict__ bet,
                            const float* __restrict__ mean, const float* __restrict__ var) {
    int tid = threadIdx.x;
    if (tid < 4 * RR) {
        int b = tid / RR, r = tid % RR;
        int qq = r / 11, pp = r % 11;
        float acc = b2[pp];
        #pragma unroll
        for (int p = 0; p < 10; p++) {
            float h1 = b1[qq];
            #pragma unroll
            for (int t = 0; t < 5; t++) h1 += w1[qq * 5 + t] * STE[(b * 5 + t) * 10 + p];
            acc += w2[pp * 10 + p] * h1;
        }
        g_theta[b][r] = fmaxf(acc, 0.f);
    }
    if (tid < 64) {
        int o = tid;
        float inv = gam[o] * rsqrtf(var[o] + 1e-5f);
        for (int c = 0; c < 32; c++) g_wt[c][o] = wm[o * 32 + c] * inv;
        g_wt[32][o] = bm[o] * inv + bet[o] - mean[o] * inv;
    }
    float* pn = (float*)g_pn;
    for (int i = tid; i < RR * NCH * 8; i += blockDim.x) pn[i] = 0.f;
}

// ---------------- init: m00 = x / max(||x||, eps) ----------------
__global__ void init_kernel(const float* __restrict__ x) {
    int chain = blockIdx.x;
    const float4* xg = (const float4*)(x + (size_t)chain * NT);
    float ss = 0.f;
    for (int i = threadIdx.x; i < NT / 4; i += 256) {
        float4 v = xg[i];
        ss += v.x * v.x + v.y * v.y + v.z * v.z + v.w * v.w;
    }
    ss = blockReduce256(ss);
    float s = 1.f / fmaxf(sqrtf(ss), 1e-8f);
    float4* r = (float4*)(g_R + (size_t)chain * NT);
    for (int i = threadIdx.x; i < NT / 4; i += 256) {
        float4 v = xg[i];
        v.x *= s; v.y *= s; v.z *= s; v.w *= s;
        r[i] = v;
    }
    if (threadIdx.x == 0) g_pn[0][chain][0] = 1.f;
}

// ---------------- spatial GEMM + fused dot epilogue ----------------
__global__ void __launch_bounds__(256) s_gemm_dots(const float* __restrict__ L,
                                                   int lastIdx, int secIdx,
                                                   int slot, int wSlot) {
    __shared__ float As[16][128];
    __shared__ float Bs[16][64];
    int chain = blockIdx.y;
    int n0 = blockIdx.x * 128;
    const float* Bg = g_R + (size_t)lastIdx * BUFSZ + (size_t)chain * NT;
    int tid = threadIdx.x;
    int ty = tid >> 4, tx = tid & 15;
    float acc[8][4];
    #pragma unroll
    for (int i = 0; i < 8; i++)
        #pragma unroll
        for (int j = 0; j < 4; j++) acc[i][j] = 0.f;

    int lin0 = tid * 2, lin1 = tid * 2 + 1;
    int ar0 = lin0 >> 2, ac0 = lin0 & 3;
    int ar1 = lin1 >> 2, ac1 = lin1 & 3;
    int bk = tid >> 4, bt = tid & 15;
    float4 pa0 = *(const float4*)(L + (size_t)(n0 + ar0) * 512 + ac0 * 4);
    float4 pa1 = *(const float4*)(L + (size_t)(n0 + ar1) * 512 + ac1 * 4);
    float4 pb  = *(const float4*)(Bg + (size_t)bk * 64 + bt * 4);

    for (int k0 = 0; k0 < 512; k0 += 16) {
        As[ac0 * 4 + 0][ar0] = pa0.x; As[ac0 * 4 + 1][ar0] = pa0.y;
        As[ac0 * 4 + 2][ar0] = pa0.z; As[ac0 * 4 + 3][ar0] = pa0.w;
        As[ac1 * 4 + 0][ar1] = pa1.x; As[ac1 * 4 + 1][ar1] = pa1.y;
        As[ac1 * 4 + 2][ar1] = pa1.z; As[ac1 * 4 + 3][ar1] = pa1.w;
        *(float4*)&Bs[bk][bt * 4] = pb;
        __syncthreads();
        if (k0 + 16 < 512) {
            int kn = k0 + 16;
            pa0 = *(const float4*)(L + (size_t)(n0 + ar0) * 512 + kn + ac0 * 4);
            pa1 = *(const float4*)(L + (size_t)(n0 + ar1) * 512 + kn + ac1 * 4);
            pb  = *(const float4*)(Bg + (size_t)(kn + bk) * 64 + bt * 4);
        }
        #pragma unroll
        for (int k = 0; k < 16; k++) {
            float4 a0 = *(const float4*)&As[k][ty * 8];
            float4 a1 = *(const float4*)&As[k][ty * 8 + 4];
            float4 bv = *(const float4*)&Bs[k][tx * 4];
            float av[8] = {a0.x, a0.y, a0.z, a0.w, a1.x, a1.y, a1.z, a1.w};
            float bb[4] = {bv.x, bv.y, bv.z, bv.w};
            #pragma unroll
            for (int i = 0; i < 8; i++)
                #pragma unroll
                for (int j = 0; j < 4; j++) acc[i][j] += av[i] * bb[j];
        }
        __syncthreads();
    }
    float* Wg = g_Wg + (size_t)wSlot * BUFSZ + (size_t)chain * NT;
    const float* Rl = g_R + (size_t)lastIdx * BUFSZ + (size_t)chain * NT;
    const float* Rs = (secIdx >= 0) ? g_R + (size_t)secIdx * BUFSZ + (size_t)chain * NT : 0;
    float d1 = 0.f, d2 = 0.f, d3 = 0.f;
    #pragma unroll
    for (int i = 0; i < 8; i++) {
        size_t off = (size_t)(n0 + ty * 8 + i) * 64 + tx * 4;
        *(float4*)(Wg + off) = make_float4(acc[i][0], acc[i][1], acc[i][2], acc[i][3]);
        float4 lv = *(const float4*)(Rl + off);
        d1 += acc[i][0] * lv.x + acc[i][1] * lv.y + acc[i][2] * lv.z + acc[i][3] * lv.w;
        if (Rs) {
            float4 sv = *(const float4*)(Rs + off);
            d2 += acc[i][0] * sv.x + acc[i][1] * sv.y + acc[i][2] * sv.z + acc[i][3] * sv.w;
            d3 += lv.x * sv.x + lv.y * sv.y + lv.z * sv.z + lv.w * sv.w;
        }
    }
    d1 = blockReduce256(d1);
    d2 = blockReduce256(d2);
    d3 = blockReduce256(d3);
    if (tid == 0) {
        g_sd[slot][chain][blockIdx.x][0] = d1;
        g_sd[slot][chain][blockIdx.x][1] = d2;
        g_sd[slot][chain][blockIdx.x][2] = d3;
    }
}

// ---------------- fused: [update -> R_new] + temporal GEMM + dots ----------------
// If updLast < 0: skip update, A-tile = g_R[outIdx] (already valid).
// Else: R_new = c1*W + c2*R[updLast] + c3*R[updSec] built in smem, stored to g_R[outIdx],
// norm partial to g_pn[outIdx]. Then W_new = R_new * Lt (row-local 64x64 tile GEMM),
// stored to g_Wg[wSlot]; dot partials to g_sd[newSlot]:
//   d1=<W_new,R_new>, d2=<W_new,R[updLast]>, d3=<R_new,R[updLast]> (dotMode=1)
__global__ void __launch_bounds__(256) ft_kernel(const float* __restrict__ Lt,
                                                 int updLast, int updSec, int outIdx,
                                                 int npart, int wSlot, int newSlot,
                                                 int dotMode) {
    __shared__ float Lts[64][64];
    __shared__ float As[64][64];
    __shared__ float Rls[64][64];
    __shared__ float cf[3];

    int chain = blockIdx.y;
    int r0 = blockIdx.x * 64;
    int tid = threadIdx.x;
    size_t base = (size_t)chain * NT + (size_t)r0 * 64;

    for (int i = tid; i < 1024; i += 256) ((float4*)Lts)[i] = ((const float4*)Lt)[i];

    float d3 = 0.f;
    if (updLast >= 0) {
        if (tid == 0) gs_coeffs(updLast, updSec, outIdx, npart, chain, cf);
        __syncthreads();
        float c1 = cf[0], c2 = cf[1], c3 = cf[2];
        const float4* wg = (const float4*)(g_Wg + (size_t)wSlot * BUFSZ + base);
        const float4* lg = (const float4*)(g_R + (size_t)updLast * BUFSZ + base);
        const float4* sg = (updSec >= 0)
            ? (const float4*)(g_R + (size_t)updSec * BUFSZ + base) : 0;
        float4* og = (float4*)(g_R + (size_t)outIdx * BUFSZ + base);
        float nrm = 0.f;
        for (int i = tid; i < 1024; i += 256) {
            float4 wv = wg[i], lv = lg[i];
            float4 rv;
            if (sg) {
                float4 sv = sg[i];
                rv.x = c1 * wv.x + c2 * lv.x + c3 * sv.x;
                rv.y = c1 * wv.y + c2 * lv.y + c3 * sv.y;
                rv.z = c1 * wv.z + c2 * lv.z + c3 * sv.z;
                rv.w = c1 * wv.w + c2 * lv.w + c3 * sv.w;
            } else {
                rv.x = c1 * wv.x + c2 * lv.x;
                rv.y = c1 * wv.y + c2 * lv.y;
                rv.z = c1 * wv.z + c2 * lv.z;
                rv.w = c1 * wv.w + c2 * lv.w;
            }
            og[i] = rv;
            ((float4*)As)[i] = rv;
            ((float4*)Rls)[i] = lv;
            nrm += rv.x * rv.x + rv.y * rv.y + rv.z * rv.z + rv.w * rv.w;
            d3 += rv.x * lv.x + rv.y * lv.y + rv.z * lv.z + rv.w * lv.w;
        }
        nrm = blockReduce256(nrm);
        if (tid == 0) g_pn[outIdx][chain][blockIdx.x] = nrm;
    } else {
        const float4* ag = (const float4*)(g_R + (size_t)outIdx * BUFSZ + base);
        for (int i = tid; i < 1024; i += 256) ((float4*)As)[i] = ag[i];
    }
    __syncthreads();

    int ty = tid >> 4, tx = tid & 15;
    float acc[4][4];
    #pragma unroll
    for (int i = 0; i < 4; i++)
        #pragma unroll
        for (int j = 0; j < 4; j++) acc[i][j] = 0.f;

    #pragma unroll 4
    for (int t0 = 0; t0 < 64; t0 += 4) {
        float4 b0 = *(const float4*)&Lts[t0 + 0][tx * 4];
        float4 b1 = *(const float4*)&Lts[t0 + 1][tx * 4];
        float4 b2 = *(const float4*)&Lts[t0 + 2][tx * 4];
        float4 b3 = *(const float4*)&Lts[t0 + 3][tx * 4];
        #pragma unroll
        for (int i = 0; i < 4; i++) {
            float4 a = *(const float4*)&As[ty * 4 + i][t0];
            acc[i][0] += a.x * b0.x + a.y * b1.x + a.z * b2.x + a.w * b3.x;
            acc[i][1] += a.x * b0.y + a.y * b1.y + a.z * b2.y + a.w * b3.y;
            acc[i][2] += a.x * b0.z + a.y * b1.z + a.z * b2.z + a.w * b3.z;
            acc[i][3] += a.x * b0.w + a.y * b1.w + a.z * b2.w + a.w * b3.w;
        }
    }

    float* Wg = g_Wg + (size_t)wSlot * BUFSZ + base;
    float d1 = 0.f, d2 = 0.f;
    #pragma unroll
    for (int i = 0; i < 4; i++) {
        int row = ty * 4 + i;
        *(float4*)(Wg + (size_t)row * 64 + tx * 4) =
            make_float4(acc[i][0], acc[i][1], acc[i][2], acc[i][3]);
        float4 rv = *(const float4*)&As[row][tx * 4];
        d1 += acc[i][0] * rv.x + acc[i][1] * rv.y + acc[i][2] * rv.z + acc[i][3] * rv.w;
        if (dotMode) {
            float4 lv = *(const float4*)&Rls[row][tx * 4];
            d2 += acc[i][0] * lv.x + acc[i][1] * lv.y + acc[i][2] * lv.z + acc[i][3] * lv.w;
        }
    }
    d1 = blockReduce256(d1);
    d2 = blockReduce256(d2);
    d3 = blockReduce256(d3);
    if (tid == 0) {
        g_sd[newSlot][chain][blockIdx.x][0] = d1;
        g_sd[newSlot][chain][blockIdx.x][1] = d2;
        g_sd[newSlot][chain][blockIdx.x][2] = d3;
    }
}

// ---------------- batched tail updates (one launch, 11 groups) ----------------
__global__ void __launch_bounds__(256) tail_kernel() {
    __shared__ float cf[3];
    int g = blockIdx.z;
    int outIdx = 6 * g + 5, updLast = 6 * g + 4, updSec = 6 * g + 3;
    int chain = blockIdx.y;
    int r0 = blockIdx.x * 64;
    int tid = threadIdx.x;
    if (tid == 0) gs_coeffs(updLast, updSec, outIdx, 8, chain, cf);
    __syncthreads();
    float c1 = cf[0], c2 = cf[1], c3 = cf[2];
    size_t base = (size_t)chain * NT + (size_t)r0 * 64;
    const float4* wg = (const float4*)(g_Wg + (size_t)g * BUFSZ + base);
    const float4* lg = (const float4*)(g_R + (size_t)updLast * BUFSZ + base);
    const float4* sg = (const float4*)(g_R + (size_t)updSec * BUFSZ + base);
    float4* og = (float4*)(g_R + (size_t)outIdx * BUFSZ + base);
    float nrm = 0.f;
    for (int i = tid; i < 1024; i += 256) {
        float4 wv = wg[i], lv = lg[i], sv = sg[i];
        float4 rv;
        rv.x = c1 * wv.x + c2 * lv.x + c3 * sv.x;
        rv.y = c1 * wv.y + c2 * lv.y + c3 * sv.y;
        rv.z = c1 * wv.z + c2 * lv.z + c3 * sv.z;
        rv.w = c1 * wv.w + c2 * lv.w + c3 * sv.w;
        og[i] = rv;
        nrm += rv.x * rv.x + rv.y * rv.y + rv.z * rv.z + rv.w * rv.w;
    }
    nrm = blockReduce256(nrm);
    if (tid == 0) g_pn[outIdx][chain][blockIdx.x] = nrm;
}

// ---------------- final: x_st + MLP + BN fused ----------------
__global__ void final_kernel(const float* __restrict__ x, float* __restrict__ out) {
    __shared__ float coef[RR][16];
    __shared__ float wsh[33][64];
    int b = blockIdx.y;
    int tid = threadIdx.x;
    for (int idx = tid; idx < RR * 16; idx += 256) {
        int r = idx >> 4, f = idx & 15;
        int c = b * 16 + f;
        float pn = 0.f;
        #pragma unroll
        for (int p = 0; p < 8; p++) pn += g_pn[r][c][p];
        float s = 1.f / fmaxf(sqrtf(pn), 1e-8f);
        coef[r][f] = g_theta[b][r] * s;
    }
    for (int idx = tid; idx < 33 * 64; idx += 256) ((float*)wsh)[idx] = ((const float*)g_wt)[idx];
    __syncthreads();

    int n = blockIdx.x * 4 + (tid >> 6);
    int t = tid & 63;
    int e = n * 64 + t;
    float yo[64];
    #pragma unroll
    for (int o = 0; o < 64; o++) yo[o] = wsh[32][o];

    #pragma unroll 1
    for (int f = 0; f < 16; f++) {
        size_t cb = (size_t)(b * 16 + f) * NT + e;
        float xv = x[cb];
        float xs = 0.f;
        #pragma unroll 11
        for (int r = 0; r < RR; r++) xs += coef[r][f] * g_R[(size_t)r * BUFSZ + cb];
        #pragma unroll
        for (int o4 = 0; o4 < 16; o4++) {
            float4 w1 = *(const float4*)&wsh[f][o4 * 4];
            float4 w2 = *(const float4*)&wsh[16 + f][o4 * 4];
            yo[o4 * 4 + 0] += w1.x * xv + w2.x * xs;
            yo[o4 * 4 + 1] += w1.y * xv + w2.y * xs;
            yo[o4 * 4 + 2] += w1.z * xv + w2.z * xs;
            yo[o4 * 4 + 3] += w1.w * xv + w2.w * xs;
        }
    }
    size_t ob = (size_t)b * 64 * NT + e;
    #pragma unroll
    for (int o = 0; o < 64; o++) out[ob + (size_t)o * NT] = yo[o];
}

// ---------------- host orchestration ----------------
extern "C" void kernel_launch(void* const* d_in, const int* in_sizes, int n_in,
                              void* d_out, int out_size) {
    const float* x   = (const float*)d_in[0];
    const float* Ls  = (const float*)d_in[1];
    const float* Lt  = (const float*)d_in[2];
    const float* STE = (const float*)d_in[3];
    const float* w1  = (const float*)d_in[4];
    const float* b1  = (const float*)d_in[5];
    const float* w2  = (const float*)d_in[6];
    const float* b2  = (const float*)d_in[7];
    const float* wm  = (const float*)d_in[8];
    const float* bm  = (const float*)d_in[9];
    const float* gam = (const float*)d_in[10];
    const float* bet = (const float*)d_in[11];
    const float* mean= (const float*)d_in[12];
    const float* var = (const float*)d_in[13];
    float* out = (float*)d_out;

    prep_kernel<<<1, 320>>>(STE, w1, b1, w2, b2, wm, bm, gam, bet, mean, var);
    init_kernel<<<64, 256>>>(x);

    dim3 gT(8, NCH);
    dim3 gS(4, NCH);

    int sPrev = 0, sPrev2 = -1;
    for (int g = 0; g <= 10; g++) {
        int s = 6 * g;
        if (g == 0) {
            // group 0: A = m00 already in g_R[0]; gemm + dots only
            ft_kernel<<<gT, 256>>>(Lt, -1, -1, 0, 0, 0, 1, 0);
        } else {
            s_gemm_dots<<<gS, 256>>>(Ls, sPrev, sPrev2, s, g);
            // spatial update (build m_{g,0}) fused with first temporal gemm
            ft_kernel<<<gT, 256>>>(Lt, sPrev, sPrev2, s, 4, g, s + 1, 0);
            sPrev2 = sPrev; sPrev = s;
        }
        for (int j = 2; j <= 5; j++) {
            int o = s + j - 1;
            ft_kernel<<<gT, 256>>>(Lt, o - 1, (j == 2) ? -1 : o - 2, o, 8, g, o + 1, 1);
        }
    }
    tail_kernel<<<dim3(8, NCH, NGRP), 256>>>();
    final_kernel<<<dim3(128, 4), 256>>>(x, out);
}

// round 7
// speedup vs baseline: 1.2963x; 1.0489x over previous
#include <cuda_runtime.h>
#include <math.h>

#define NCH   64
#define NT    32768
#define RR    66
#define BUFSZ ((size_t)NCH * (size_t)NT)
#define NGRP  11
#define WSLOTS 12
#define WSP   11   // spatial W slot

__device__ float g_R[(size_t)RR * BUFSZ];          // 553 MB basis buffers (raw)
__device__ float g_Wg[(size_t)WSLOTS * BUFSZ];     // 96 MB per-group GEMM workspace
__device__ float g_pn[RR][NCH][8];                 // norm^2 partials
__device__ float g_sd[RR][NCH][8][3];              // dot partials per gemm-block
__device__ float g_theta[4][RR];
__device__ float g_wt[33][64];

__device__ __forceinline__ float blockReduce256(float v) {
    __shared__ float sh[8];
    __syncthreads();
    #pragma unroll
    for (int o = 16; o > 0; o >>= 1) v += __shfl_down_sync(0xffffffffu, v, o);
    if ((threadIdx.x & 31) == 0) sh[threadIdx.x >> 5] = v;
    __syncthreads();
    if (threadIdx.x == 0) {
        float s = 0.f;
        #pragma unroll
        for (int i = 0; i < 8; i++) s += sh[i];
        sh[0] = s;
    }
    __syncthreads();
    return sh[0];
}

// Gram-Schmidt coefficients from stored partials (deferred normalization)
__device__ __forceinline__ void gs_coeffs(int updLast, int updSec, int outIdx,
                                          int npart, int chain, float* cf) {
    float pnl = 0.f;
    #pragma unroll
    for (int p = 0; p < 8; p++) pnl += g_pn[updLast][chain][p];
    float sl = 1.f / fmaxf(sqrtf(pnl), 1e-8f);
    float D1 = 0.f, D2 = 0.f, D3 = 0.f;
    for (int p = 0; p < npart; p++) {
        D1 += g_sd[outIdx][chain][p][0];
        D2 += g_sd[outIdx][chain][p][1];
        D3 += g_sd[outIdx][chain][p][2];
    }
    float d1 = sl * sl * D1;
    float c3 = 0.f;
    if (updSec >= 0) {
        float pns = 0.f;
        #pragma unroll
        for (int p = 0; p < 8; p++) pns += g_pn[updSec][chain][p];
        float ssc = 1.f / fmaxf(sqrtf(pns), 1e-8f);
        float dd2 = sl * ssc * D2;
        float dd3 = sl * ssc * D3;
        c3 = -(dd2 - d1 * dd3) * ssc;
    }
    cf[0] = sl; cf[1] = -d1 * sl; cf[2] = c3;
}

// ---------------- prep ----------------
__global__ void prep_kernel(const float* __restrict__ STE,
                            const float* __restrict__ w1, const float* __restrict__ b1,
                            const float* __restrict__ w2, const float* __restrict__ b2,
                            const float* __restrict__ wm, const float* __restrict__ bm,
                            const float* __restrict__ gam, const float* __restrict__ bet,
                            const float* __restrict__ mean, const float* __restrict__ var) {
    int tid = threadIdx.x;
    if (tid < 4 * RR) {
        int b = tid / RR, r = tid % RR;
        int qq = r / 11, pp = r % 11;
        float acc = b2[pp];
        #pragma unroll
        for (int p = 0; p < 10; p++) {
            float h1 = b1[qq];
            #pragma unroll
            for (int t = 0; t < 5; t++) h1 += w1[qq * 5 + t] * STE[(b * 5 + t) * 10 + p];
            acc += w2[pp * 10 + p] * h1;
        }
        g_theta[b][r] = fmaxf(acc, 0.f);
    }
    if (tid < 64) {
        int o = tid;
        float inv = gam[o] * rsqrtf(var[o] + 1e-5f);
        for (int c = 0; c < 32; c++) g_wt[c][o] = wm[o * 32 + c] * inv;
        g_wt[32][o] = bm[o] * inv + bet[o] - mean[o] * inv;
    }
    float* pn = (float*)g_pn;
    for (int i = tid; i < RR * NCH * 8; i += blockDim.x) pn[i] = 0.f;
}

// ---------------- init: m00 = x / max(||x||, eps) ----------------
__global__ void init_kernel(const float* __restrict__ x) {
    int chain = blockIdx.x;
    const float4* xg = (const float4*)(x + (size_t)chain * NT);
    float ss = 0.f;
    for (int i = threadIdx.x; i < NT / 4; i += 256) {
        float4 v = xg[i];
        ss += v.x * v.x + v.y * v.y + v.z * v.z + v.w * v.w;
    }
    ss = blockReduce256(ss);
    float s = 1.f / fmaxf(sqrtf(ss), 1e-8f);
    float4* r = (float4*)(g_R + (size_t)chain * NT);
    for (int i = threadIdx.x; i < NT / 4; i += 256) {
        float4 v = xg[i];
        v.x *= s; v.y *= s; v.z *= s; v.w *= s;
        r[i] = v;
    }
    if (threadIdx.x == 0) g_pn[0][chain][0] = 1.f;
}

// ---------------- spatial GEMM + fused dot epilogue ----------------
__global__ void __launch_bounds__(256) s_gemm_dots(const float* __restrict__ L,
                                                   int lastIdx, int secIdx, int slot) {
    __shared__ float As[16][128];
    __shared__ float Bs[16][64];
    int chain = blockIdx.y;
    int n0 = blockIdx.x * 128;
    const float* Bg = g_R + (size_t)lastIdx * BUFSZ + (size_t)chain * NT;
    int tid = threadIdx.x;
    int ty = tid >> 4, tx = tid & 15;
    float acc[8][4];
    #pragma unroll
    for (int i = 0; i < 8; i++)
        #pragma unroll
        for (int j = 0; j < 4; j++) acc[i][j] = 0.f;

    int lin0 = tid * 2, lin1 = tid * 2 + 1;
    int ar0 = lin0 >> 2, ac0 = lin0 & 3;
    int ar1 = lin1 >> 2, ac1 = lin1 & 3;
    int bk = tid >> 4, bt = tid & 15;
    float4 pa0 = *(const float4*)(L + (size_t)(n0 + ar0) * 512 + ac0 * 4);
    float4 pa1 = *(const float4*)(L + (size_t)(n0 + ar1) * 512 + ac1 * 4);
    float4 pb  = *(const float4*)(Bg + (size_t)bk * 64 + bt * 4);

    for (int k0 = 0; k0 < 512; k0 += 16) {
        As[ac0 * 4 + 0][ar0] = pa0.x; As[ac0 * 4 + 1][ar0] = pa0.y;
        As[ac0 * 4 + 2][ar0] = pa0.z; As[ac0 * 4 + 3][ar0] = pa0.w;
        As[ac1 * 4 + 0][ar1] = pa1.x; As[ac1 * 4 + 1][ar1] = pa1.y;
        As[ac1 * 4 + 2][ar1] = pa1.z; As[ac1 * 4 + 3][ar1] = pa1.w;
        *(float4*)&Bs[bk][bt * 4] = pb;
        __syncthreads();
        if (k0 + 16 < 512) {
            int kn = k0 + 16;
            pa0 = *(const float4*)(L + (size_t)(n0 + ar0) * 512 + kn + ac0 * 4);
            pa1 = *(const float4*)(L + (size_t)(n0 + ar1) * 512 + kn + ac1 * 4);
            pb  = *(const float4*)(Bg + (size_t)(kn + bk) * 64 + bt * 4);
        }
        #pragma unroll
        for (int k = 0; k < 16; k++) {
            float4 a0 = *(const float4*)&As[k][ty * 8];
            float4 a1 = *(const float4*)&As[k][ty * 8 + 4];
            float4 bv = *(const float4*)&Bs[k][tx * 4];
            float av[8] = {a0.x, a0.y, a0.z, a0.w, a1.x, a1.y, a1.z, a1.w};
            float bb[4] = {bv.x, bv.y, bv.z, bv.w};
            #pragma unroll
            for (int i = 0; i < 8; i++)
                #pragma unroll
                for (int j = 0; j < 4; j++) acc[i][j] += av[i] * bb[j];
        }
        __syncthreads();
    }
    float* Wg = g_Wg + (size_t)WSP * BUFSZ + (size_t)chain * NT;
    const float* Rl = g_R + (size_t)lastIdx * BUFSZ + (size_t)chain * NT;
    const float* Rs = (secIdx >= 0) ? g_R + (size_t)secIdx * BUFSZ + (size_t)chain * NT : 0;
    float d1 = 0.f, d2 = 0.f, d3 = 0.f;
    #pragma unroll
    for (int i = 0; i < 8; i++) {
        size_t off = (size_t)(n0 + ty * 8 + i) * 64 + tx * 4;
        *(float4*)(Wg + off) = make_float4(acc[i][0], acc[i][1], acc[i][2], acc[i][3]);
        float4 lv = *(const float4*)(Rl + off);
        d1 += acc[i][0] * lv.x + acc[i][1] * lv.y + acc[i][2] * lv.z + acc[i][3] * lv.w;
        if (Rs) {
            float4 sv = *(const float4*)(Rs + off);
            d2 += acc[i][0] * sv.x + acc[i][1] * sv.y + acc[i][2] * sv.z + acc[i][3] * sv.w;
            d3 += lv.x * sv.x + lv.y * sv.y + lv.z * sv.z + lv.w * sv.w;
        }
    }
    d1 = blockReduce256(d1);
    d2 = blockReduce256(d2);
    d3 = blockReduce256(d3);
    if (tid == 0) {
        g_sd[slot][chain][blockIdx.x][0] = d1;
        g_sd[slot][chain][blockIdx.x][1] = d2;
        g_sd[slot][chain][blockIdx.x][2] = d3;
    }
}

// ---------------- standalone update (spatial seeds) ----------------
__global__ void __launch_bounds__(256) upd_kernel(int wSlot, int updLast, int updSec,
                                                  int outIdx, int npart) {
    __shared__ float cf[3];
    int chain = blockIdx.y;
    int r0 = blockIdx.x * 64;
    int tid = threadIdx.x;
    if (tid == 0) gs_coeffs(updLast, updSec, outIdx, npart, chain, cf);
    __syncthreads();
    float c1 = cf[0], c2 = cf[1], c3 = cf[2];
    size_t base = (size_t)chain * NT + (size_t)r0 * 64;
    const float4* wg = (const float4*)(g_Wg + (size_t)wSlot * BUFSZ + base);
    const float4* lg = (const float4*)(g_R + (size_t)updLast * BUFSZ + base);
    const float4* sg = (updSec >= 0) ? (const float4*)(g_R + (size_t)updSec * BUFSZ + base) : 0;
    float4* og = (float4*)(g_R + (size_t)outIdx * BUFSZ + base);
    float nrm = 0.f;
    for (int i = tid; i < 1024; i += 256) {
        float4 wv = wg[i], lv = lg[i];
        float4 rv;
        if (sg) {
            float4 sv = sg[i];
            rv.x = c1 * wv.x + c2 * lv.x + c3 * sv.x;
            rv.y = c1 * wv.y + c2 * lv.y + c3 * sv.y;
            rv.z = c1 * wv.z + c2 * lv.z + c3 * sv.z;
            rv.w = c1 * wv.w + c2 * lv.w + c3 * sv.w;
        } else {
            rv.x = c1 * wv.x + c2 * lv.x;
            rv.y = c1 * wv.y + c2 * lv.y;
            rv.z = c1 * wv.z + c2 * lv.z;
            rv.w = c1 * wv.w + c2 * lv.w;
        }
        og[i] = rv;
        nrm += rv.x * rv.x + rv.y * rv.y + rv.z * rv.z + rv.w * rv.w;
    }
    nrm = blockReduce256(nrm);
    if (tid == 0) g_pn[outIdx][chain][blockIdx.x] = nrm;
}

// ---------------- wave kernel: all 11 groups advance one temporal step ----------------
// blockIdx.z = group g; wave index j passed as param.
// j==0: A = R[6g] (seed), GEMM + d1 dots -> slot 6g+1, W -> g_Wg[g].
// j>=1: update R[6g+j] from W=g_Wg[g], updLast=6g+j-1, updSec=(j==1?-1:6g+j-2);
//       then GEMM, dots -> slot 6g+j+1 (d1,d2,d3 vs updated-last).
__global__ void __launch_bounds__(256) wave_kernel(const float* __restrict__ Lt, int j) {
    __shared__ float Lts[64][64];
    __shared__ float As[64][64];
    __shared__ float Rls[64][64];
    __shared__ float cf[3];

    int g = blockIdx.z;
    int chain = blockIdx.y;
    int r0 = blockIdx.x * 64;
    int tid = threadIdx.x;
    size_t base = (size_t)chain * NT + (size_t)r0 * 64;
    int seed = 6 * g;

    for (int i = tid; i < 1024; i += 256) ((float4*)Lts)[i] = ((const float4*)Lt)[i];

    float d3 = 0.f;
    if (j >= 1) {
        int outIdx = seed + j;
        int updLast = seed + j - 1;
        int updSec = (j == 1) ? -1 : seed + j - 2;
        if (tid == 0) gs_coeffs(updLast, updSec, outIdx, 8, chain, cf);
        __syncthreads();
        float c1 = cf[0], c2 = cf[1], c3 = cf[2];
        const float4* wg = (const float4*)(g_Wg + (size_t)g * BUFSZ + base);
        const float4* lg = (const float4*)(g_R + (size_t)updLast * BUFSZ + base);
        const float4* sg = (updSec >= 0)
            ? (const float4*)(g_R + (size_t)updSec * BUFSZ + base) : 0;
        float4* og = (float4*)(g_R + (size_t)outIdx * BUFSZ + base);
        float nrm = 0.f;
        for (int i = tid; i < 1024; i += 256) {
            float4 wv = wg[i], lv = lg[i];
            float4 rv;
            if (sg) {
                float4 sv = sg[i];
                rv.x = c1 * wv.x + c2 * lv.x + c3 * sv.x;
                rv.y = c1 * wv.y + c2 * lv.y + c3 * sv.y;
                rv.z = c1 * wv.z + c2 * lv.z + c3 * sv.z;
                rv.w = c1 * wv.w + c2 * lv.w + c3 * sv.w;
            } else {
                rv.x = c1 * wv.x + c2 * lv.x;
                rv.y = c1 * wv.y + c2 * lv.y;
                rv.z = c1 * wv.z + c2 * lv.z;
                rv.w = c1 * wv.w + c2 * lv.w;
            }
            og[i] = rv;
            ((float4*)As)[i] = rv;
            ((float4*)Rls)[i] = lv;
            nrm += rv.x * rv.x + rv.y * rv.y + rv.z * rv.z + rv.w * rv.w;
            d3 += rv.x * lv.x + rv.y * lv.y + rv.z * lv.z + rv.w * lv.w;
        }
        nrm = blockReduce256(nrm);
        if (tid == 0) g_pn[outIdx][chain][blockIdx.x] = nrm;
    } else {
        const float4* ag = (const float4*)(g_R + (size_t)seed * BUFSZ + base);
        for (int i = tid; i < 1024; i += 256) ((float4*)As)[i] = ag[i];
    }
    __syncthreads();

    int ty = tid >> 4, tx = tid & 15;
    float acc[4][4];
    #pragma unroll
    for (int i = 0; i < 4; i++)
        #pragma unroll
        for (int jj = 0; jj < 4; jj++) acc[i][jj] = 0.f;

    #pragma unroll 4
    for (int t0 = 0; t0 < 64; t0 += 4) {
        float4 b0 = *(const float4*)&Lts[t0 + 0][tx * 4];
        float4 b1 = *(const float4*)&Lts[t0 + 1][tx * 4];
        float4 b2 = *(const float4*)&Lts[t0 + 2][tx * 4];
        float4 b3 = *(const float4*)&Lts[t0 + 3][tx * 4];
        #pragma unroll
        for (int i = 0; i < 4; i++) {
            float4 a = *(const float4*)&As[ty * 4 + i][t0];
            acc[i][0] += a.x * b0.x + a.y * b1.x + a.z * b2.x + a.w * b3.x;
            acc[i][1] += a.x * b0.y + a.y * b1.y + a.z * b2.y + a.w * b3.y;
            acc[i][2] += a.x * b0.z + a.y * b1.z + a.z * b2.z + a.w * b3.z;
            acc[i][3] += a.x * b0.w + a.y * b1.w + a.z * b2.w + a.w * b3.w;
        }
    }

    float* Wg = g_Wg + (size_t)g * BUFSZ + base;
    float d1 = 0.f, d2 = 0.f;
    #pragma unroll
    for (int i = 0; i < 4; i++) {
        int row = ty * 4 + i;
        *(float4*)(Wg + (size_t)row * 64 + tx * 4) =
            make_float4(acc[i][0], acc[i][1], acc[i][2], acc[i][3]);
        float4 rv = *(const float4*)&As[row][tx * 4];
        d1 += acc[i][0] * rv.x + acc[i][1] * rv.y + acc[i][2] * rv.z + acc[i][3] * rv.w;
        if (j >= 1) {
            float4 lv = *(const float4*)&Rls[row][tx * 4];
            d2 += acc[i][0] * lv.x + acc[i][1] * lv.y + acc[i][2] * lv.z + acc[i][3] * lv.w;
        }
    }
    d1 = blockReduce256(d1);
    d2 = blockReduce256(d2);
    d3 = blockReduce256(d3);
    if (tid == 0) {
        int newSlot = seed + j + 1;
        g_sd[newSlot][chain][blockIdx.x][0] = d1;
        g_sd[newSlot][chain][blockIdx.x][1] = d2;
        g_sd[newSlot][chain][blockIdx.x][2] = d3;
    }
}

// ---------------- batched tail updates (one launch, 11 groups) ----------------
__global__ void __launch_bounds__(256) tail_kernel() {
    __shared__ float cf[3];
    int g = blockIdx.z;
    int outIdx = 6 * g + 5, updLast = 6 * g + 4, updSec = 6 * g + 3;
    int chain = blockIdx.y;
    int r0 = blockIdx.x * 64;
    int tid = threadIdx.x;
    if (tid == 0) gs_coeffs(updLast, updSec, outIdx, 8, chain, cf);
    __syncthreads();
    float c1 = cf[0], c2 = cf[1], c3 = cf[2];
    size_t base = (size_t)chain * NT + (size_t)r0 * 64;
    const float4* wg = (const float4*)(g_Wg + (size_t)g * BUFSZ + base);
    const float4* lg = (const float4*)(g_R + (size_t)updLast * BUFSZ + base);
    const float4* sg = (const float4*)(g_R + (size_t)updSec * BUFSZ + base);
    float4* og = (float4*)(g_R + (size_t)outIdx * BUFSZ + base);
    float nrm = 0.f;
    for (int i = tid; i < 1024; i += 256) {
        float4 wv = wg[i], lv = lg[i], sv = sg[i];
        float4 rv;
        rv.x = c1 * wv.x + c2 * lv.x + c3 * sv.x;
        rv.y = c1 * wv.y + c2 * lv.y + c3 * sv.y;
        rv.z = c1 * wv.z + c2 * lv.z + c3 * sv.z;
        rv.w = c1 * wv.w + c2 * lv.w + c3 * sv.w;
        og[i] = rv;
        nrm += rv.x * rv.x + rv.y * rv.y + rv.z * rv.z + rv.w * rv.w;
    }
    nrm = blockReduce256(nrm);
    if (tid == 0) g_pn[outIdx][chain][blockIdx.x] = nrm;
}

// ---------------- final: x_st + MLP + BN fused ----------------
__global__ void final_kernel(const float* __restrict__ x, float* __restrict__ out) {
    __shared__ float coef[RR][16];
    __shared__ float wsh[33][64];
    int b = blockIdx.y;
    int tid = threadIdx.x;
    for (int idx = tid; idx < RR * 16; idx += 256) {
        int r = idx >> 4, f = idx & 15;
        int c = b * 16 + f;
        float pn = 0.f;
        #pragma unroll
        for (int p = 0; p < 8; p++) pn += g_pn[r][c][p];
        float s = 1.f / fmaxf(sqrtf(pn), 1e-8f);
        coef[r][f] = g_theta[b][r] * s;
    }
    for (int idx = tid; idx < 33 * 64; idx += 256) ((float*)wsh)[idx] = ((const float*)g_wt)[idx];
    __syncthreads();

    int n = blockIdx.x * 4 + (tid >> 6);
    int t = tid & 63;
    int e = n * 64 + t;
    float yo[64];
    #pragma unroll
    for (int o = 0; o < 64; o++) yo[o] = wsh[32][o];

    #pragma unroll 1
    for (int f = 0; f < 16; f++) {
        size_t cb = (size_t)(b * 16 + f) * NT + e;
        float xv = x[cb];
        float xs = 0.f;
        #pragma unroll 11
        for (int r = 0; r < RR; r++) xs += coef[r][f] * g_R[(size_t)r * BUFSZ + cb];
        #pragma unroll
        for (int o4 = 0; o4 < 16; o4++) {
            float4 w1 = *(const float4*)&wsh[f][o4 * 4];
            float4 w2 = *(const float4*)&wsh[16 + f][o4 * 4];
            yo[o4 * 4 + 0] += w1.x * xv + w2.x * xs;
            yo[o4 * 4 + 1] += w1.y * xv + w2.y * xs;
            yo[o4 * 4 + 2] += w1.z * xv + w2.z * xs;
            yo[o4 * 4 + 3] += w1.w * xv + w2.w * xs;
        }
    }
    size_t ob = (size_t)b * 64 * NT + e;
    #pragma unroll
    for (int o = 0; o < 64; o++) out[ob + (size_t)o * NT] = yo[o];
}

// ---------------- host orchestration ----------------
extern "C" void kernel_launch(void* const* d_in, const int* in_sizes, int n_in,
                              void* d_out, int out_size) {
    const float* x   = (const float*)d_in[0];
    const float* Ls  = (const float*)d_in[1];
    const float* Lt  = (const float*)d_in[2];
    const float* STE = (const float*)d_in[3];
    const float* w1  = (const float*)d_in[4];
    const float* b1  = (const float*)d_in[5];
    const float* w2  = (const float*)d_in[6];
    const float* b2  = (const float*)d_in[7];
    const float* wm  = (const float*)d_in[8];
    const float* bm  = (const float*)d_in[9];
    const float* gam = (const float*)d_in[10];
    const float* bet = (const float*)d_in[11];
    const float* mean= (const float*)d_in[12];
    const float* var = (const float*)d_in[13];
    float* out = (float*)d_out;

    prep_kernel<<<1, 320>>>(STE, w1, b1, w2, b2, wm, bm, gam, bet, mean, var);
    init_kernel<<<64, 256>>>(x);

    dim3 gS(4, NCH);
    dim3 gU(8, NCH);
    dim3 gW(8, NCH, NGRP);

    // spatial chain: materialize all seeds m_{g,0} at slots 6g
    for (int g = 1; g <= 10; g++) {
        int last = 6 * (g - 1);
        int sec = (g >= 2) ? 6 * (g - 2) : -1;
        s_gemm_dots<<<gS, 256>>>(Ls, last, sec, 6 * g);
        upd_kernel<<<gU, 256>>>(WSP, last, sec, 6 * g, 4);
    }
    // temporal waves: all 11 groups advance together
    for (int j = 0; j < 5; j++) {
        wave_kernel<<<gW, 256>>>(Lt, j);
    }
    tail_kernel<<<gW, 256>>>();
    final_kernel<<<dim3(128, 4), 256>>>(x, out);
}